// round 16
// baseline (speedup 1.0000x reference)
#include <cuda_runtime.h>
#include <cuda_bf16.h>
#include <cooperative_groups.h>

namespace cg = cooperative_groups;

// Problem constants (pinned by the reference)
#define B_DIM   64
#define S_DIM   8192
#define D_DIM   64
#define N_BINS  256                 // output bins; bin 256 = dummy (T >= 256)
#define NCHUNK  4                   // CTAs (cluster size) per batch in the sort
#define CHUNK_S (S_DIM / NCHUNK)    // 2048 tokens per chunk
#define NBIN1   (N_BINS + 1)        // 257 (incl. dummy)
#define STARTS_PER_B 258

#define BINS_PER_CTA 8              // K2: one warp per bin, 8 bins per CTA
#define STAGE_CAP    1024           // smem (x,w) slots per CTA (8 KB); E[need]=256
#define PIPE         12             // cp.async pipeline depth (tokens in flight/warp)

// Scratch (allocation-free rule: __device__ globals)
__device__ int2 g_sorted[B_DIM * S_DIM];          // (x, w-bits), bin-contiguous per batch
__device__ int  g_start [B_DIM * STARTS_PER_B];   // per-batch exclusive bin starts

// cp.async helpers (LDGSTS)
__device__ __forceinline__ void cp_async8(unsigned int smem_addr, const void* gptr) {
    asm volatile("cp.async.ca.shared.global [%0], [%1], 8;\n"
                 :: "r"(smem_addr), "l"(gptr));
}
#define CP_COMMIT()  asm volatile("cp.async.commit_group;\n" ::)
#define CP_WAIT(Nn)  asm volatile("cp.async.wait_group %0;\n" :: "n"(Nn))

// ---------------------------------------------------------------------------
// K1: fused per-batch counting sort, SINGLE atomic pass. (FROZEN: best
// measured config. The atomicAdd return value doubles as the within-bin
// rank, making the local scatter atomic-free.)
// ---------------------------------------------------------------------------
__global__ __launch_bounds__(512, 2) __cluster_dims__(NCHUNK, 1, 1)
void k_sort(const float* __restrict__ T, const int* __restrict__ X,
            const float* __restrict__ embedW)
{
    __shared__ int            hist [NBIN1];
    __shared__ int            scanT[NBIN1];    // batch-wide totals (scanned)
    __shared__ int            scanL[NBIN1];    // own-chunk hist (scanned)
    __shared__ int            delta[NBIN1];    // p_local + delta[bin] = global pos
    __shared__ int            lbase[NBIN1];    // local (chunk) bin starts
    __shared__ unsigned int   sbr  [CHUNK_S];  // packed (rank<<16 | bin), original order
    __shared__ unsigned short sbin2[CHUNK_S];  // bin at locally-sorted position
    __shared__ int            sx   [CHUNK_S];  // token id at locally-sorted position

    cg::cluster_group cluster = cg::this_cluster();
    const int c   = (int)cluster.block_rank();     // chunk 0..3
    const int b   = blockIdx.x >> 2;               // batch
    const int tid = threadIdx.x;

    for (int i = tid; i < NBIN1; i += 512) hist[i] = 0;
    __syncthreads();

    // --- A: bin + histogram; the atomic's return value IS the rank ---
    const float* Tb = T + b * S_DIM + c * CHUNK_S;
    #pragma unroll 4
    for (int s = tid; s < CHUNK_S; s += 512) {
        float t  = Tb[s];
        int bin  = (t < 256.0f) ? (int)t : N_BINS; // t >= 0 -> (int)t == floor
        int rank = atomicAdd(&hist[bin], 1);
        sbr[s]   = ((unsigned int)rank << 16) | (unsigned int)bin;
    }
    cluster.sync();

    // --- B: peer hist gather + dual scan ---
    int tot = 0, part = 0, own = 0;
    if (tid < NBIN1) {
        #pragma unroll
        for (int cc = 0; cc < NCHUNK; ++cc) {
            const int* rh = cluster.map_shared_rank(hist, cc);
            int h = rh[tid];
            tot += h;
            if (cc < c) part += h;
        }
        own = hist[tid];
        scanT[tid] = tot;
        scanL[tid] = own;
    }
    __syncthreads();

    for (int d = 1; d < NBIN1; d <<= 1) {
        int vT = 0, vL = 0;
        if (tid < NBIN1 && tid >= d) { vT = scanT[tid - d]; vL = scanL[tid - d]; }
        __syncthreads();
        if (tid < NBIN1) { scanT[tid] += vT; scanL[tid] += vL; }
        __syncthreads();
    }

    if (tid < NBIN1) {
        int gbase  = scanT[tid] - tot;   // batch-wide bin start
        int lb     = scanL[tid] - own;   // local (chunk) bin start
        lbase[tid] = lb;
        delta[tid] = gbase + part - lb;
        if (c == 0) {
            g_start[b * STARTS_PER_B + tid] = gbase;
            if (tid == 0) g_start[b * STARTS_PER_B + NBIN1] = S_DIM;
        }
    }
    __syncthreads();

    // --- C: atomic-free local scatter (position = lbase[bin] + rank) ---
    const int* Xb = X + b * S_DIM + c * CHUNK_S;
    #pragma unroll 4
    for (int s = tid; s < CHUNK_S; s += 512) {
        unsigned int br = sbr[s];
        int bin  = (int)(br & 0xFFFFu);
        int lpos = lbase[bin] + (int)(br >> 16);
        sx[lpos]    = Xb[s];
        sbin2[lpos] = (unsigned short)bin;
    }
    __syncthreads();

    // --- D: coalesced copy-out + weight compute ---
    int2* dst = g_sorted + b * S_DIM;
    #pragma unroll 4
    for (int p = tid; p < CHUNK_S; p += 512) {
        int   x   = sx[p];
        int   bin = sbin2[p];
        float w   = __expf(__ldg(&embedW[x]));
        dst[p + delta[bin]] = make_int2(x, __float_as_int(w));
    }

    cluster.sync();   // peers may still be reading our smem hist
}

// ---------------------------------------------------------------------------
// K2: one CTA per (batch, 8 consecutive bins); one warp per bin; the (x,w)
// range is staged once into smem (coalesced). NEW: the embedding-row gather
// is a per-warp cp.async pipeline of depth PIPE=12 — each lane cp.asyncs its
// 8B slice of the 256B row into a smem ring, so 12 x 256B = 3 KB/warp sits
// in flight at ZERO register cost (registers were the in-flight cap in every
// prior variant). One commit_group per token (empty groups included) keeps
// the invariant "token j lives in group j", so wait_group(PIPE-1) before
// consuming token j guarantees its row has landed.
//   issue  : LDS x from stage -> cp.async.ca 8B -> commit
//   consume: wait_group(P-1) -> LDS.64 ring row + LDS w -> 2 FFMA
// smem: 8KB stage + 24KB ring ≈ 33KB -> 6 CTAs/SM (48 warps, same occ).
// ---------------------------------------------------------------------------
__global__ __launch_bounds__(256)
void k_bin_reduce(const float* __restrict__ embedX, float* __restrict__ out)
{
    __shared__ int2   stage[STAGE_CAP];
    __shared__ int    sgs[BINS_PER_CTA + 1];
    __shared__ float2 ring[BINS_PER_CTA][PIPE][32];   // 24 KB

    const int tid  = threadIdx.x;
    const int wid  = tid >> 5;                 // warp in CTA = bin offset 0..7
    const int lane = tid & 31;
    const int b    = blockIdx.x >> 5;          // batch 0..63
    const int bin0 = (blockIdx.x & 31) * BINS_PER_CTA;

    if (tid <= BINS_PER_CTA)
        sgs[tid] = g_start[b * STARTS_PER_B + bin0 + tid];
    __syncthreads();

    const int s0c = sgs[0];
    const int cnt = sgs[BINS_PER_CTA] - s0c;
    const int2* gxw = g_sorted + b * S_DIM + s0c;

    const bool staged = (cnt <= STAGE_CAP);
    if (staged) {
        for (int i = tid; i < cnt; i += 256)
            stage[i] = gxw[i];
    }
    __syncthreads();

    const int s0 = sgs[wid]     - s0c;         // this warp's bin, local offsets
    const int s1 = sgs[wid + 1] - s0c;
    const int n  = s1 - s0;

    const float2* ex = reinterpret_cast<const float2*>(embedX);
    float2 acc = make_float2(0.0f, 0.0f);

    if (staged) {
        // lane's fixed 8B slot within each ring row
        const unsigned int rb =
            (unsigned int)__cvta_generic_to_shared(&ring[wid][0][lane]);

        // prime the pipeline: tokens 0..PIPE-1 -> groups 0..PIPE-1
        #pragma unroll
        for (int k = 0; k < PIPE; ++k) {
            if (k < n) {
                int x = stage[s0 + k].x;
                cp_async8(rb + (unsigned int)k * 256u, &ex[x * 32 + lane]);
            }
            CP_COMMIT();
        }

        int slot = 0;
        for (int i = 0; i < n; ++i) {
            CP_WAIT(PIPE - 1);                 // group i (token i) complete
            float2 e = ring[wid][slot][lane];  // LDS.64, conflict-free
            float  w = __int_as_float(stage[s0 + i].y);
            acc.x = fmaf(w, e.x, acc.x);
            acc.y = fmaf(w, e.y, acc.y);

            int k = i + PIPE;                  // refill the slot just consumed
            if (k < n) {
                int x = stage[s0 + k].x;
                cp_async8(rb + (unsigned int)slot * 256u, &ex[x * 32 + lane]);
            }
            CP_COMMIT();
            slot = (slot + 1 == PIPE) ? 0 : slot + 1;
        }
        CP_WAIT(0);                            // drain (all remaining empty)
    } else {                                   // safety net (never for this input)
        #pragma unroll 4
        for (int i = s0; i < s1; ++i) {
            int2  xw = __ldg(&gxw[i]);
            float w  = __int_as_float(xw.y);
            float2 e = __ldg(&ex[xw.x * 32 + lane]);
            acc.x = fmaf(w, e.x, acc.x);
            acc.y = fmaf(w, e.y, acc.y);
        }
    }

    float inv = 1.0f / ((float)n + 1e-6f);
    reinterpret_cast<float2*>(out)[(b * N_BINS + bin0 + wid) * 32 + lane] =
        make_float2(acc.x * inv, acc.y * inv);
}

// ---------------------------------------------------------------------------
// Inputs (metadata order):
//   d_in[0] : T        float32 [B, S]
//   d_in[1] : X_ids    int32   [B, S]
//   d_in[2] : embedX_w float32 [N_TOKENS+1, 64]
//   d_in[3] : embedW_w float32 [N_TOKENS+1, 1]
// Output    : float32 [B, 256, 64]
// ---------------------------------------------------------------------------
extern "C" void kernel_launch(void* const* d_in, const int* in_sizes, int n_in,
                              void* d_out, int out_size)
{
    const float* T      = (const float*)d_in[0];
    const int*   X_ids  = (const int*)  d_in[1];
    const float* embedX = (const float*)d_in[2];
    const float* embedW = (const float*)d_in[3];
    float*       out    = (float*)d_out;

    k_sort      <<<B_DIM * NCHUNK, 512>>>(T, X_ids, embedW);
    k_bin_reduce<<<B_DIM * (N_BINS / BINS_PER_CTA), 256>>>(embedX, out);
}

// round 17
// speedup vs baseline: 1.5030x; 1.5030x over previous
#include <cuda_runtime.h>
#include <cuda_bf16.h>
#include <cooperative_groups.h>

namespace cg = cooperative_groups;

// Problem constants (pinned by the reference)
#define B_DIM   64
#define S_DIM   8192
#define D_DIM   64
#define N_BINS  256                 // output bins; bin 256 = dummy (T >= 256)
#define NCHUNK  4                   // CTAs (cluster size) per batch in the sort
#define CHUNK_S (S_DIM / NCHUNK)    // 2048 tokens per chunk
#define NBIN1   (N_BINS + 1)        // 257 (incl. dummy)
#define STARTS_PER_B 258

#define BINS_PER_CTA 8              // K2: 8 bins per CTA, balanced token windows
#define STAGE_CAP    1024           // smem (x,w) slots per CTA (8 KB); E[need]=256

// Scratch (allocation-free rule: __device__ globals)
__device__ int2 g_sorted[B_DIM * S_DIM];          // (x, w-bits), bin-contiguous per batch
__device__ int  g_start [B_DIM * STARTS_PER_B];   // per-batch exclusive bin starts

// ---------------------------------------------------------------------------
// K1: fused per-batch counting sort, SINGLE atomic pass. (FROZEN: best
// measured config. The atomicAdd return value doubles as the within-bin
// rank, making the local scatter atomic-free.)
// ---------------------------------------------------------------------------
__global__ __launch_bounds__(512, 2) __cluster_dims__(NCHUNK, 1, 1)
void k_sort(const float* __restrict__ T, const int* __restrict__ X,
            const float* __restrict__ embedW)
{
    __shared__ int            hist [NBIN1];
    __shared__ int            scanT[NBIN1];    // batch-wide totals (scanned)
    __shared__ int            scanL[NBIN1];    // own-chunk hist (scanned)
    __shared__ int            delta[NBIN1];    // p_local + delta[bin] = global pos
    __shared__ int            lbase[NBIN1];    // local (chunk) bin starts
    __shared__ unsigned int   sbr  [CHUNK_S];  // packed (rank<<16 | bin), original order
    __shared__ unsigned short sbin2[CHUNK_S];  // bin at locally-sorted position
    __shared__ int            sx   [CHUNK_S];  // token id at locally-sorted position

    cg::cluster_group cluster = cg::this_cluster();
    const int c   = (int)cluster.block_rank();     // chunk 0..3
    const int b   = blockIdx.x >> 2;               // batch
    const int tid = threadIdx.x;

    for (int i = tid; i < NBIN1; i += 512) hist[i] = 0;
    __syncthreads();

    // --- A: bin + histogram; the atomic's return value IS the rank ---
    const float* Tb = T + b * S_DIM + c * CHUNK_S;
    #pragma unroll 4
    for (int s = tid; s < CHUNK_S; s += 512) {
        float t  = Tb[s];
        int bin  = (t < 256.0f) ? (int)t : N_BINS; // t >= 0 -> (int)t == floor
        int rank = atomicAdd(&hist[bin], 1);
        sbr[s]   = ((unsigned int)rank << 16) | (unsigned int)bin;
    }
    cluster.sync();

    // --- B: peer hist gather + dual scan ---
    int tot = 0, part = 0, own = 0;
    if (tid < NBIN1) {
        #pragma unroll
        for (int cc = 0; cc < NCHUNK; ++cc) {
            const int* rh = cluster.map_shared_rank(hist, cc);
            int h = rh[tid];
            tot += h;
            if (cc < c) part += h;
        }
        own = hist[tid];
        scanT[tid] = tot;
        scanL[tid] = own;
    }
    __syncthreads();

    for (int d = 1; d < NBIN1; d <<= 1) {
        int vT = 0, vL = 0;
        if (tid < NBIN1 && tid >= d) { vT = scanT[tid - d]; vL = scanL[tid - d]; }
        __syncthreads();
        if (tid < NBIN1) { scanT[tid] += vT; scanL[tid] += vL; }
        __syncthreads();
    }

    if (tid < NBIN1) {
        int gbase  = scanT[tid] - tot;   // batch-wide bin start
        int lb     = scanL[tid] - own;   // local (chunk) bin start
        lbase[tid] = lb;
        delta[tid] = gbase + part - lb;
        if (c == 0) {
            g_start[b * STARTS_PER_B + tid] = gbase;
            if (tid == 0) g_start[b * STARTS_PER_B + NBIN1] = S_DIM;
        }
    }
    __syncthreads();

    // --- C: atomic-free local scatter (position = lbase[bin] + rank) ---
    const int* Xb = X + b * S_DIM + c * CHUNK_S;
    #pragma unroll 4
    for (int s = tid; s < CHUNK_S; s += 512) {
        unsigned int br = sbr[s];
        int bin  = (int)(br & 0xFFFFu);
        int lpos = lbase[bin] + (int)(br >> 16);
        sx[lpos]    = Xb[s];
        sbin2[lpos] = (unsigned short)bin;
    }
    __syncthreads();

    // --- D: coalesced copy-out + weight compute ---
    int2* dst = g_sorted + b * S_DIM;
    #pragma unroll 4
    for (int p = tid; p < CHUNK_S; p += 512) {
        int   x   = sx[p];
        int   bin = sbin2[p];
        float w   = __expf(__ldg(&embedW[x]));
        dst[p + delta[bin]] = make_int2(x, __float_as_int(w));
    }

    cluster.sync();   // peers may still be reading our smem hist
}

// ---------------------------------------------------------------------------
// K2: one CTA per (batch, 8 consecutive bins). The contiguous (x,w) range is
// staged once into smem (R15 mechanism, frozen). NEW: LOAD-BALANCED token
// partition — each warp processes an equal window of cnt/8 tokens instead of
// one Poisson(32) bin (critical path E[max of 8 Poisson(32)] ~ 46 -> 32
// tokens, ~30% of CTA time). Bin boundaries are handled by a two-level loop:
// the inner loop is the proven exact-count unroll-4 broadcast-LDS gather with
// NO in-body branches; the outer loop flushes the register accumulator into
// per-bin smem float accumulators (2 smem atomicAdds/lane per bin crossing,
// ~2-3 crossings per warp). Warp w then finalizes bin w (divide, store).
// ---------------------------------------------------------------------------
__global__ __launch_bounds__(256)
void k_bin_reduce(const float* __restrict__ embedX, float* __restrict__ out)
{
    __shared__ int2  stage[STAGE_CAP];
    __shared__ int   sgs[BINS_PER_CTA + 1];
    __shared__ float ssum[BINS_PER_CTA][D_DIM];   // 2 KB per-bin accumulators

    const int tid  = threadIdx.x;
    const int wid  = tid >> 5;
    const int lane = tid & 31;
    const int b    = blockIdx.x >> 5;          // batch 0..63
    const int bin0 = (blockIdx.x & 31) * BINS_PER_CTA;

    if (tid <= BINS_PER_CTA)
        sgs[tid] = g_start[b * STARTS_PER_B + bin0 + tid];
    // zero the 512 accumulator floats (2 per thread)
    {
        float* sf = &ssum[0][0];
        sf[tid]       = 0.0f;
        sf[tid + 256] = 0.0f;
    }
    __syncthreads();

    const int s0c = sgs[0];
    const int cnt = sgs[BINS_PER_CTA] - s0c;
    const int2* gxw = g_sorted + b * S_DIM + s0c;

    const bool staged = (cnt <= STAGE_CAP);
    if (staged) {
        for (int i = tid; i < cnt; i += 256)
            stage[i] = gxw[i];
    }
    __syncthreads();

    // balanced window for this warp
    const int chunk = (cnt + BINS_PER_CTA - 1) / BINS_PER_CTA;
    const int lo = min(wid * chunk, cnt);
    const int hi = min(lo + chunk, cnt);

    const float2* ex = reinterpret_cast<const float2*>(embedX);

    if (lo < hi) {
        // locate starting bin (warp-uniform; <=8 smem reads)
        int bin = 0;
        while (sgs[bin + 1] - s0c <= lo) ++bin;
        int binEnd = sgs[bin + 1] - s0c;

        float2 acc = make_float2(0.0f, 0.0f);
        int i = lo;
        if (staged) {
            for (;;) {
                const int stop = min(binEnd, hi);
                #pragma unroll 4
                for (; i < stop; ++i) {            // branch-free inner body
                    int2  xw = stage[i];           // broadcast LDS.64
                    float w  = __int_as_float(xw.y);
                    float2 e = __ldg(&ex[xw.x * 32 + lane]);
                    acc.x = fmaf(w, e.x, acc.x);
                    acc.y = fmaf(w, e.y, acc.y);
                }
                atomicAdd(&ssum[bin][2 * lane],     acc.x);
                atomicAdd(&ssum[bin][2 * lane + 1], acc.y);
                acc = make_float2(0.0f, 0.0f);
                if (i >= hi) break;
                ++bin;
                while (sgs[bin + 1] - s0c <= i) ++bin;   // skip empty bins
                binEnd = sgs[bin + 1] - s0c;
            }
        } else {                                   // safety net (never for this input)
            for (;;) {
                const int stop = min(binEnd, hi);
                #pragma unroll 4
                for (; i < stop; ++i) {
                    int2  xw = __ldg(&gxw[i]);
                    float w  = __int_as_float(xw.y);
                    float2 e = __ldg(&ex[xw.x * 32 + lane]);
                    acc.x = fmaf(w, e.x, acc.x);
                    acc.y = fmaf(w, e.y, acc.y);
                }
                atomicAdd(&ssum[bin][2 * lane],     acc.x);
                atomicAdd(&ssum[bin][2 * lane + 1], acc.y);
                acc = make_float2(0.0f, 0.0f);
                if (i >= hi) break;
                ++bin;
                while (sgs[bin + 1] - s0c <= i) ++bin;
                binEnd = sgs[bin + 1] - s0c;
            }
        }
    }
    __syncthreads();

    // warp w finalizes bin w
    const int n = sgs[wid + 1] - sgs[wid];
    float inv = 1.0f / ((float)n + 1e-6f);
    reinterpret_cast<float2*>(out)[(b * N_BINS + bin0 + wid) * 32 + lane] =
        make_float2(ssum[wid][2 * lane] * inv, ssum[wid][2 * lane + 1] * inv);
}

// ---------------------------------------------------------------------------
// Inputs (metadata order):
//   d_in[0] : T        float32 [B, S]
//   d_in[1] : X_ids    int32   [B, S]
//   d_in[2] : embedX_w float32 [N_TOKENS+1, 64]
//   d_in[3] : embedW_w float32 [N_TOKENS+1, 1]
// Output    : float32 [B, 256, 64]
// ---------------------------------------------------------------------------
extern "C" void kernel_launch(void* const* d_in, const int* in_sizes, int n_in,
                              void* d_out, int out_size)
{
    const float* T      = (const float*)d_in[0];
    const int*   X_ids  = (const int*)  d_in[1];
    const float* embedX = (const float*)d_in[2];
    const float* embedW = (const float*)d_in[3];
    float*       out    = (float*)d_out;

    k_sort      <<<B_DIM * NCHUNK, 512>>>(T, X_ids, embedW);
    k_bin_reduce<<<B_DIM * (N_BINS / BINS_PER_CTA), 256>>>(embedX, out);
}